// round 4
// baseline (speedup 1.0000x reference)
#include <cuda_runtime.h>
#include <cstdint>

#define Bsz 256
#define Tsz 512
#define Hsz 128
#define Gsz 512          // 4*H
#define GS  384          // gate rows of Whh kept in shared memory
#define REC_SMEM (32*GS*16 + 64*16 + 2*Gsz*4)   // ws + h4 + gsm = 201728 B

// ---- scratch (device globals: the allowed allocation mechanism) ----
__device__ float  g_xg[(size_t)Tsz * Bsz * Gsz];   // 256 MB
__device__ float  g_hA[(size_t)Tsz * Bsz * Hsz];   // 64 MB
__device__ float  g_hB[(size_t)Tsz * Bsz * Hsz];   // 64 MB
__device__ float4 g_WqH[32 * Gsz];                 // transposed Whh (k-chunk major)
__device__ float4 g_WqI[32 * Gsz];                 // transposed Wih (layers 1,2)

__device__ __forceinline__ float sigf(float x) { return 1.f / (1.f + __expf(-x)); }

// ---------------------------------------------------------------------------
// Transpose W[512][128] -> Wq[kk][g] = float4(W[g][4kk..4kk+3]), kk=0..31
// ---------------------------------------------------------------------------
__global__ void k_tr(const float* __restrict__ W, float4* __restrict__ Wq) {
    int i  = blockIdx.x * 256 + threadIdx.x;   // i = g*32 + kk, 16384 total
    int g  = i >> 5;
    int kk = i & 31;
    float4 v = *(const float4*)(W + g * Hsz + kk * 4);
    Wq[kk * Gsz + g] = v;
}

// ---------------------------------------------------------------------------
// Layer-0 input gates: xg[p][g] = dot(x[b,t,:8], Wih0[g,:8]) + bih[g]+bhh[g]
// p = t*256 + b. 64 p-rows per block, thread = gate g.
// ---------------------------------------------------------------------------
__global__ void __launch_bounds__(512) k_xg0(const float* __restrict__ x,
                                             const float* __restrict__ Wih,
                                             const float* __restrict__ bih,
                                             const float* __restrict__ bhh,
                                             float* __restrict__ xg) {
    __shared__ float xs[64 * 8];
    const int tid = threadIdx.x;
    const float4* wr = (const float4*)(Wih + tid * 8);
    float4 wa = wr[0], wb = wr[1];
    float bias = bih[tid] + bhh[tid];
    const int p0 = blockIdx.x * 64;
    {
        int q = tid >> 3, i = tid & 7;
        int p = p0 + q;
        int t = p >> 8, b = p & 255;
        xs[tid] = x[((size_t)b * Tsz + t) * 8 + i];
    }
    __syncthreads();
    float* op = xg + (size_t)p0 * Gsz + tid;
    #pragma unroll 4
    for (int q = 0; q < 64; q++) {
        const float* xr = xs + q * 8;
        float a = bias + wa.x * xr[0] + wa.y * xr[1] + wa.z * xr[2] + wa.w * xr[3]
                       + wb.x * xr[4] + wb.y * xr[5] + wb.z * xr[6] + wb.w * xr[7];
        op[(size_t)q * Gsz] = a;
    }
}

// ---------------------------------------------------------------------------
// xg GEMM for layers 1,2: xg[p][g] = sum_k hin[p][k]*Wih[g][k] + bih[g]+bhh[g]
// 64 p-rows per block; Wq = transposed Wih (L2-resident, 256 KB).
// ---------------------------------------------------------------------------
__global__ void __launch_bounds__(512) k_gemm(const float* __restrict__ hin,
                                              const float* __restrict__ bih,
                                              const float* __restrict__ bhh,
                                              const float4* __restrict__ Wq,
                                              float* __restrict__ xg) {
    __shared__ float4 hs[64 * 32];           // 64 rows x 128 floats = 32 KB
    const int tid = threadIdx.x;
    const size_t p0 = (size_t)blockIdx.x * 64;
    const float4* hin4 = (const float4*)(hin + p0 * Hsz);
    #pragma unroll
    for (int i = 0; i < 4; i++) hs[tid + i * 512] = hin4[tid + i * 512];
    __syncthreads();
    float bias = bih[tid] + bhh[tid];
    for (int rb = 0; rb < 4; rb++) {
        float acc[16];
        #pragma unroll
        for (int r = 0; r < 16; r++) acc[r] = bias;
        #pragma unroll 4
        for (int kk = 0; kk < 32; kk++) {
            float4 w = __ldg(Wq + kk * Gsz + tid);
            #pragma unroll
            for (int r = 0; r < 16; r++) {
                float4 h4 = hs[(rb * 16 + r) * 32 + kk];   // warp broadcast
                acc[r] += w.x * h4.x + w.y * h4.y + w.z * h4.z + w.w * h4.w;
            }
        }
        float* op = xg + (p0 + rb * 16) * Gsz + tid;
        #pragma unroll
        for (int r = 0; r < 16; r++) op[(size_t)r * Gsz] = acc[r];
    }
}

// ---------------------------------------------------------------------------
// LSTM recurrence, one layer. 128 blocks x 512 threads; block owns batch rows
// b0, b0+1. Thread g computes gate row g; threads 0..255 own (b, j) cell state.
// Wq rows [0,GS) live in smem, rows [GS,512) stream from L2 each step.
// ---------------------------------------------------------------------------
__global__ void __launch_bounds__(512) k_rec(const float* __restrict__ xg,
                                             const float4* __restrict__ Wq,
                                             float* __restrict__ hout) {
    extern __shared__ float4 sm[];
    float4* ws  = sm;                         // [32][GS]
    float4* h4  = sm + 32 * GS;               // [2][32]  (2 rows x 128 floats)
    float*  gsm = (float*)(h4 + 64);          // [2][512]

    const int tid = threadIdx.x;
    for (int i = tid; i < 32 * GS; i += 512) {
        int kk = i / GS, g = i - kk * GS;
        ws[i] = Wq[kk * Gsz + g];
    }
    if (tid < 64) h4[tid] = make_float4(0.f, 0.f, 0.f, 0.f);
    __syncthreads();

    const int b0 = blockIdx.x * 2;
    float c0 = 0.f, c1 = 0.f;

    for (int t = 0; t < Tsz; t++) {
        const size_t p0 = (size_t)t * Bsz + b0;
        float acc0 = xg[p0 * Gsz + tid];
        float acc1 = xg[(p0 + 1) * Gsz + tid];
        if (tid < GS) {
            #pragma unroll 8
            for (int kk = 0; kk < 32; kk++) {
                float4 w  = ws[kk * GS + tid];
                float4 ha = h4[kk];
                float4 hb = h4[32 + kk];
                acc0 += w.x * ha.x + w.y * ha.y + w.z * ha.z + w.w * ha.w;
                acc1 += w.x * hb.x + w.y * hb.y + w.z * hb.z + w.w * hb.w;
            }
        } else {
            #pragma unroll 8
            for (int kk = 0; kk < 32; kk++) {
                float4 w  = __ldg(Wq + kk * Gsz + tid);
                float4 ha = h4[kk];
                float4 hb = h4[32 + kk];
                acc0 += w.x * ha.x + w.y * ha.y + w.z * ha.z + w.w * ha.w;
                acc1 += w.x * hb.x + w.y * hb.y + w.z * hb.z + w.w * hb.w;
            }
        }
        gsm[tid]       = acc0;
        gsm[512 + tid] = acc1;
        __syncthreads();
        if (tid < 256) {
            int b = tid >> 7, j = tid & 127;
            const float* gb = gsm + b * 512;
            float ig = sigf(gb[j]);
            float fg = sigf(gb[j + 128]);
            float gg = tanhf(gb[j + 256]);
            float og = sigf(gb[j + 384]);
            float c  = b ? c1 : c0;
            c = fg * c + ig * gg;
            if (b) c1 = c; else c0 = c;
            float h = og * tanhf(c);
            ((float*)h4)[b * 128 + j] = h;
            hout[(p0 + b) * Hsz + j]  = h;
        }
        __syncthreads();
    }
}

// ---------------------------------------------------------------------------
// FC head: out[b][o] = dot(h_final[b], Wfc[o]) + bfc[o]   (256 x 3)
// ---------------------------------------------------------------------------
__global__ void k_fc(const float* __restrict__ hA,
                     const float* __restrict__ Wfc,
                     const float* __restrict__ bfc,
                     float* __restrict__ out) {
    int tid = threadIdx.x;                 // 768 threads
    int b = tid / 3, o = tid - b * 3;
    const float* h = hA + ((size_t)(Tsz - 1) * Bsz + b) * Hsz;
    const float* w = Wfc + o * Hsz;
    float a = bfc[o];
    #pragma unroll 8
    for (int k = 0; k < Hsz; k++) a += h[k] * w[k];
    out[tid] = a;
}

// ---------------------------------------------------------------------------
extern "C" void kernel_launch(void* const* d_in, const int* in_sizes, int n_in,
                              void* d_out, int out_size) {
    const float* x   = (const float*)d_in[0];
    const float* Wih[3] = {(const float*)d_in[1], (const float*)d_in[5], (const float*)d_in[9]};
    const float* Whh[3] = {(const float*)d_in[2], (const float*)d_in[6], (const float*)d_in[10]};
    const float* bih[3] = {(const float*)d_in[3], (const float*)d_in[7], (const float*)d_in[11]};
    const float* bhh[3] = {(const float*)d_in[4], (const float*)d_in[8], (const float*)d_in[12]};
    const float* Wfc = (const float*)d_in[13];
    const float* bfc = (const float*)d_in[14];
    float* out = (float*)d_out;

    float *xg, *hA, *hB;
    float4 *WqH, *WqI;
    cudaGetSymbolAddress((void**)&xg,  g_xg);
    cudaGetSymbolAddress((void**)&hA,  g_hA);
    cudaGetSymbolAddress((void**)&hB,  g_hB);
    cudaGetSymbolAddress((void**)&WqH, g_WqH);
    cudaGetSymbolAddress((void**)&WqI, g_WqI);

    cudaFuncSetAttribute(k_rec, cudaFuncAttributeMaxDynamicSharedMemorySize, REC_SMEM);

    const int PBLK = (Tsz * Bsz) / 64;     // 2048

    // layer 0
    k_xg0<<<PBLK, 512>>>(x, Wih[0], bih[0], bhh[0], xg);
    k_tr<<<64, 256>>>(Whh[0], WqH);
    k_rec<<<128, 512, REC_SMEM>>>(xg, WqH, hA);

    // layer 1
    k_tr<<<64, 256>>>(Wih[1], WqI);
    k_gemm<<<PBLK, 512>>>(hA, bih[1], bhh[1], WqI, xg);
    k_tr<<<64, 256>>>(Whh[1], WqH);
    k_rec<<<128, 512, REC_SMEM>>>(xg, WqH, hB);

    // layer 2
    k_tr<<<64, 256>>>(Wih[2], WqI);
    k_gemm<<<PBLK, 512>>>(hB, bih[2], bhh[2], WqI, xg);
    k_tr<<<64, 256>>>(Whh[2], WqH);
    k_rec<<<128, 512, REC_SMEM>>>(xg, WqH, hA);

    // FC head
    k_fc<<<1, 768>>>(hA, Wfc, bfc, out);
}

// round 5
// speedup vs baseline: 1.0320x; 1.0320x over previous
#include <cuda_runtime.h>
#include <cstdint>

#define Bsz 256
#define Tsz 512
#define Hsz 128
#define Gsz 512          // 4*H
#define GS  384          // gate rows of Whh kept in shared memory (12 warps)
#define REC_SMEM (32*GS*16 + 64*16 + 2*Gsz*4)   // ws + h2 + gsm = 201728 B

typedef unsigned long long u64;

// ---- scratch (device globals: the allowed allocation mechanism) ----
__device__ float  g_xg[(size_t)Tsz * Bsz * Gsz];   // 256 MB
__device__ float  g_hA[(size_t)Tsz * Bsz * Hsz];   // 64 MB
__device__ float  g_hB[(size_t)Tsz * Bsz * Hsz];   // 64 MB
__device__ float4 g_WqH[32 * Gsz];                 // transposed Whh (k-chunk major)
__device__ float4 g_WqI[32 * Gsz];                 // transposed Wih (layers 1,2)

// packed fp32x2 FMA: d = a*b + d (elementwise on 2 floats in a 64-bit reg)
__device__ __forceinline__ void ffma2(u64& d, u64 a, u64 b) {
    asm("fma.rn.f32x2 %0, %1, %2, %0;" : "+l"(d) : "l"(a), "l"(b));
}
__device__ __forceinline__ float2 unpk(u64 v) {
    float2 r;
    asm("mov.b64 {%0, %1}, %2;" : "=f"(r.x), "=f"(r.y) : "l"(v));
    return r;
}
__device__ __forceinline__ float tanh_hw(float x) {
    float r;
    asm("tanh.approx.f32 %0, %1;" : "=f"(r) : "f"(x));
    return r;
}
__device__ __forceinline__ float sig_hw(float x) {
    return fmaf(0.5f, tanh_hw(0.5f * x), 0.5f);
}

// ---------------------------------------------------------------------------
// Transpose W[512][128] -> Wq[kk][g] = float4(W[g][4kk..4kk+3]), kk=0..31
// ---------------------------------------------------------------------------
__global__ void k_tr(const float* __restrict__ W, float4* __restrict__ Wq) {
    int i  = blockIdx.x * 256 + threadIdx.x;   // i = g*32 + kk
    int g  = i >> 5;
    int kk = i & 31;
    float4 v = *(const float4*)(W + g * Hsz + kk * 4);
    Wq[kk * Gsz + g] = v;
}

// ---------------------------------------------------------------------------
// Layer-0 input gates: xg[p][g] = dot(x[b,t,:8], Wih0[g,:8]) + bih[g]+bhh[g]
// p = t*256 + b. 64 p-rows per block, thread = gate g.
// ---------------------------------------------------------------------------
__global__ void __launch_bounds__(512) k_xg0(const float* __restrict__ x,
                                             const float* __restrict__ Wih,
                                             const float* __restrict__ bih,
                                             const float* __restrict__ bhh,
                                             float* __restrict__ xg) {
    __shared__ float xs[64 * 8];
    const int tid = threadIdx.x;
    const float4* wr = (const float4*)(Wih + tid * 8);
    float4 wa = wr[0], wb = wr[1];
    float bias = bih[tid] + bhh[tid];
    const int p0 = blockIdx.x * 64;
    {
        int q = tid >> 3, i = tid & 7;
        int p = p0 + q;
        int t = p >> 8, b = p & 255;
        xs[tid] = x[((size_t)b * Tsz + t) * 8 + i];
    }
    __syncthreads();
    float* op = xg + (size_t)p0 * Gsz + tid;
    #pragma unroll 4
    for (int q = 0; q < 64; q++) {
        const float* xr = xs + q * 8;
        float a = bias + wa.x * xr[0] + wa.y * xr[1] + wa.z * xr[2] + wa.w * xr[3]
                       + wb.x * xr[4] + wb.y * xr[5] + wb.z * xr[6] + wb.w * xr[7];
        op[(size_t)q * Gsz] = a;
    }
}

// ---------------------------------------------------------------------------
// xg GEMM for layers 1,2 (f32x2): xg[p][g] = sum_k hin[p][k]*Wih[g][k] + bias
// 64 p-rows per block; Wq = transposed Wih (L2-resident, 256 KB).
// ---------------------------------------------------------------------------
__global__ void __launch_bounds__(512) k_gemm(const float* __restrict__ hin,
                                              const float* __restrict__ bih,
                                              const float* __restrict__ bhh,
                                              const float4* __restrict__ Wq,
                                              float* __restrict__ xg) {
    __shared__ ulonglong2 hs[64 * 32];       // 64 rows x 128 floats = 32 KB
    const int tid = threadIdx.x;
    const size_t p0 = (size_t)blockIdx.x * 64;
    const ulonglong2* hin2 = (const ulonglong2*)(hin + p0 * Hsz);
    #pragma unroll
    for (int i = 0; i < 4; i++) hs[tid + i * 512] = hin2[tid + i * 512];
    __syncthreads();
    const float bias = bih[tid] + bhh[tid];
    const ulonglong2* Wq2 = (const ulonglong2*)Wq;
    for (int rb = 0; rb < 4; rb++) {
        u64 acc[16];
        #pragma unroll
        for (int r = 0; r < 16; r++) acc[r] = 0ull;
        #pragma unroll 2
        for (int kk = 0; kk < 32; kk++) {
            ulonglong2 w = Wq2[kk * Gsz + tid];
            #pragma unroll
            for (int r = 0; r < 16; r++) {
                ulonglong2 h = hs[(rb * 16 + r) * 32 + kk];   // warp broadcast
                ffma2(acc[r], w.x, h.x);
                ffma2(acc[r], w.y, h.y);
            }
        }
        float* op = xg + (p0 + rb * 16) * Gsz + tid;
        #pragma unroll
        for (int r = 0; r < 16; r++) {
            float2 u = unpk(acc[r]);
            op[(size_t)r * Gsz] = bias + (u.x + u.y);
        }
    }
}

// ---------------------------------------------------------------------------
// LSTM recurrence, one layer. 128 blocks x 512 threads; block owns batch rows
// b0, b0+1. Thread g computes gate row g via f32x2 FMA; threads 0..255 own
// the (b, j) cell state. Whh rows [0,GS) in smem, rows [GS,512) stream from L2.
// xg for step t+1 is prefetched during step t's compute.
// ---------------------------------------------------------------------------
__global__ void __launch_bounds__(512) k_rec(const float* __restrict__ xg,
                                             const float4* __restrict__ Wq,
                                             float* __restrict__ hout) {
    extern __shared__ ulonglong2 sm2[];
    ulonglong2* ws  = sm2;                    // [32][GS]
    ulonglong2* h2  = sm2 + 32 * GS;          // [2][32]  (2 rows x 128 floats)
    float*      gsm = (float*)(h2 + 64);      // [2][512]

    const int tid = threadIdx.x;
    const ulonglong2* Wq2 = (const ulonglong2*)Wq;
    for (int i = tid; i < 32 * GS; i += 512) {
        int kk = i / GS, g = i - kk * GS;
        ws[i] = Wq2[kk * Gsz + g];
    }
    if (tid < 64) h2[tid] = make_ulonglong2(0ull, 0ull);
    __syncthreads();

    const int b0 = blockIdx.x * 2;
    float c0 = 0.f, c1 = 0.f;
    const float* xp = xg + (size_t)b0 * Gsz + tid;   // step stride = Bsz*Gsz
    float nx0 = xp[0];
    float nx1 = xp[Gsz];

    for (int t = 0; t < Tsz; t++) {
        const float cx0 = nx0, cx1 = nx1;
        if (t + 1 < Tsz) {                 // prefetch next step's xg (DRAM)
            nx0 = xp[(size_t)(t + 1) * Bsz * Gsz];
            nx1 = xp[(size_t)(t + 1) * Bsz * Gsz + Gsz];
        }
        u64 a0 = 0ull, a1 = 0ull, e0 = 0ull, e1 = 0ull;
        if (tid < GS) {
            #pragma unroll 8
            for (int kk = 0; kk < 32; kk++) {
                ulonglong2 w  = ws[kk * GS + tid];
                ulonglong2 ha = h2[kk];           // broadcast
                ulonglong2 hb = h2[32 + kk];      // broadcast
                ffma2(a0, w.x, ha.x); ffma2(a1, w.y, ha.y);
                ffma2(e0, w.x, hb.x); ffma2(e1, w.y, hb.y);
            }
        } else {
            #pragma unroll 8
            for (int kk = 0; kk < 32; kk++) {
                ulonglong2 w  = Wq2[kk * Gsz + tid];   // L2-resident stream
                ulonglong2 ha = h2[kk];
                ulonglong2 hb = h2[32 + kk];
                ffma2(a0, w.x, ha.x); ffma2(a1, w.y, ha.y);
                ffma2(e0, w.x, hb.x); ffma2(e1, w.y, hb.y);
            }
        }
        {
            float2 u = unpk(a0), v = unpk(a1);
            gsm[tid] = cx0 + ((u.x + u.y) + (v.x + v.y));
            float2 p = unpk(e0), q = unpk(e1);
            gsm[512 + tid] = cx1 + ((p.x + p.y) + (q.x + q.y));
        }
        __syncthreads();
        if (tid < 256) {
            int b = tid >> 7, j = tid & 127;
            const float* gb = gsm + b * 512;
            float ig = sig_hw(gb[j]);
            float fg = sig_hw(gb[j + 128]);
            float gg = tanh_hw(gb[j + 256]);
            float og = sig_hw(gb[j + 384]);
            float c  = b ? c1 : c0;
            c = fg * c + ig * gg;
            if (b) c1 = c; else c0 = c;
            float h = og * tanh_hw(c);
            ((float*)h2)[b * 128 + j] = h;
            hout[((size_t)t * Bsz + b0 + b) * Hsz + j] = h;
        }
        __syncthreads();
    }
}

// ---------------------------------------------------------------------------
// FC head: out[b][o] = dot(h_final[b], Wfc[o]) + bfc[o]   (256 x 3)
// ---------------------------------------------------------------------------
__global__ void k_fc(const float* __restrict__ hA,
                     const float* __restrict__ Wfc,
                     const float* __restrict__ bfc,
                     float* __restrict__ out) {
    int tid = threadIdx.x;                 // 768 threads
    int b = tid / 3, o = tid - b * 3;
    const float* h = hA + ((size_t)(Tsz - 1) * Bsz + b) * Hsz;
    const float* w = Wfc + o * Hsz;
    float a = bfc[o];
    #pragma unroll 8
    for (int k = 0; k < Hsz; k++) a += h[k] * w[k];
    out[tid] = a;
}

// ---------------------------------------------------------------------------
extern "C" void kernel_launch(void* const* d_in, const int* in_sizes, int n_in,
                              void* d_out, int out_size) {
    const float* x   = (const float*)d_in[0];
    const float* Wih[3] = {(const float*)d_in[1], (const float*)d_in[5], (const float*)d_in[9]};
    const float* Whh[3] = {(const float*)d_in[2], (const float*)d_in[6], (const float*)d_in[10]};
    const float* bih[3] = {(const float*)d_in[3], (const float*)d_in[7], (const float*)d_in[11]};
    const float* bhh[3] = {(const float*)d_in[4], (const float*)d_in[8], (const float*)d_in[12]};
    const float* Wfc = (const float*)d_in[13];
    const float* bfc = (const float*)d_in[14];
    float* out = (float*)d_out;

    float *xg, *hA, *hB;
    float4 *WqH, *WqI;
    cudaGetSymbolAddress((void**)&xg,  g_xg);
    cudaGetSymbolAddress((void**)&hA,  g_hA);
    cudaGetSymbolAddress((void**)&hB,  g_hB);
    cudaGetSymbolAddress((void**)&WqH, g_WqH);
    cudaGetSymbolAddress((void**)&WqI, g_WqI);

    cudaFuncSetAttribute(k_rec, cudaFuncAttributeMaxDynamicSharedMemorySize, REC_SMEM);

    const int PBLK = (Tsz * Bsz) / 64;     // 2048

    // layer 0
    k_xg0<<<PBLK, 512>>>(x, Wih[0], bih[0], bhh[0], xg);
    k_tr<<<64, 256>>>(Whh[0], WqH);
    k_rec<<<128, 512, REC_SMEM>>>(xg, WqH, hA);

    // layer 1
    k_tr<<<64, 256>>>(Wih[1], WqI);
    k_gemm<<<PBLK, 512>>>(hA, bih[1], bhh[1], WqI, xg);
    k_tr<<<64, 256>>>(Whh[1], WqH);
    k_rec<<<128, 512, REC_SMEM>>>(xg, WqH, hB);

    // layer 2
    k_tr<<<64, 256>>>(Wih[2], WqI);
    k_gemm<<<PBLK, 512>>>(hB, bih[2], bhh[2], WqI, xg);
    k_tr<<<64, 256>>>(Whh[2], WqH);
    k_rec<<<128, 512, REC_SMEM>>>(xg, WqH, hA);

    // FC head
    k_fc<<<1, 768>>>(hA, Wfc, bfc, out);
}